// round 1
// baseline (speedup 1.0000x reference)
#include <cuda_runtime.h>

#define H      64
#define E_PER  300000
#define NB     64
#define N0     100000
#define N1     20000
#define N2     50000
#define N3     80000
#define NTOT   250000   // N0+N1+N2+N3

// ---------------- static device scratch (no allocations allowed) ----------------
__device__ float        g_feat0[NTOT * H];   // layer-0 accumulator / layer-1 input
__device__ float        g_feat1[NTOT * H];   // layer-1 accumulator / pooled input
__device__ float        g_tmp[N0 * H];       // per-relation scatter target (max Nd)
__device__ float        g_als[N0];           // attention logits (src side)
__device__ float        g_ald[N0];           // attention logits (dst side)
__device__ unsigned int g_m[N0];             // segment max (order-encoded uint)
__device__ float        g_z[N0];             // segment softmax denominator
__device__ float        g_p[E_PER];          // per-edge score, then exp(score-m)
__device__ float        g_wsv[H];            // Wsrc @ asrc   (per relation)
__device__ float        g_wdv[H];            // Wdst @ adst   (per relation)
__device__ float        g_pool[NB * 2 * H];  // [B][128] pooled sums (var | con)
__device__ float        g_cnt[2 * NB];       // node counts per graph (var, con)

// ------------- order-preserving float<->uint encoding for atomicMax -------------
__device__ __forceinline__ unsigned enc_f(float f) {
    unsigned u = __float_as_uint(f);
    return (u & 0x80000000u) ? ~u : (u | 0x80000000u);
}
__device__ __forceinline__ float dec_f(unsigned u) {
    return (u & 0x80000000u) ? __uint_as_float(u & 0x7FFFFFFFu)
                             : __uint_as_float(~u);
}
#define ENC_NEG_INF 0x007FFFFFu   // enc(-inf)

__device__ __forceinline__ const float* in_feat(const float* ext, int buf, int off) {
    if (buf < 0) return ext;
    const float* base = (buf == 0) ? g_feat0 : g_feat1;
    return base + (size_t)off * H;
}

// ---------------------------------- kernels -------------------------------------

__global__ void zero_feat(int buf) {
    int i = blockIdx.x * blockDim.x + threadIdx.x;
    if (i < NTOT * H / 4) {
        float4* p4 = (float4*)((buf == 0) ? g_feat0 : g_feat1);
        p4[i] = make_float4(0.f, 0.f, 0.f, 0.f);
    }
}

// wsv[k] = sum_j Wsrc[k][j]*asrc[j] ; wdv[k] = sum_j Wdst[k][j]*adst[j]
__global__ void prep_kernel(const float* __restrict__ Ws, const float* __restrict__ as_,
                            const float* __restrict__ Wd, const float* __restrict__ ad_) {
    int t = threadIdx.x;   // 128
    float s = 0.f;
    if (t < 64) {
        #pragma unroll
        for (int j = 0; j < H; j++) s += Ws[t * H + j] * as_[j];
        g_wsv[t] = s;
    } else {
        int k = t - 64;
        #pragma unroll
        for (int j = 0; j < H; j++) s += Wd[k * H + j] * ad_[j];
        g_wdv[k] = s;
    }
}

// warp per node over [0, Ns+Nd): computes al_s / al_d, inits m,z, zeroes tmp rows
__global__ void alpha_kernel(const float* __restrict__ xs_ext, const float* __restrict__ xd_ext,
                             int buf, int soff, int doff, int Ns, int Nd) {
    int warp = threadIdx.x >> 5, lane = threadIdx.x & 31;
    int gw = blockIdx.x * 8 + warp;
    if (gw < Ns) {
        const float* x = in_feat(xs_ext, buf, soff);
        size_t base = (size_t)gw * H;
        float v = x[base + lane] * g_wsv[lane] + x[base + 32 + lane] * g_wsv[32 + lane];
        #pragma unroll
        for (int o = 16; o; o >>= 1) v += __shfl_xor_sync(0xffffffffu, v, o);
        if (lane == 0) g_als[gw] = v;
    } else if (gw < Ns + Nd) {
        int j = gw - Ns;
        const float* x = in_feat(xd_ext, buf, doff);
        size_t base = (size_t)j * H;
        float v = x[base + lane] * g_wdv[lane] + x[base + 32 + lane] * g_wdv[32 + lane];
        #pragma unroll
        for (int o = 16; o; o >>= 1) v += __shfl_xor_sync(0xffffffffu, v, o);
        if (lane == 0) { g_ald[j] = v; g_m[j] = ENC_NEG_INF; g_z[j] = 0.f; }
        g_tmp[base + lane] = 0.f;
        g_tmp[base + 32 + lane] = 0.f;
    }
}

__global__ void edge_score_max(const int* __restrict__ src, const int* __restrict__ dst) {
    int e = blockIdx.x * blockDim.x + threadIdx.x;
    if (e >= E_PER) return;
    int d = dst[e];
    float sc = g_als[src[e]] + g_ald[d];
    sc = sc > 0.f ? sc : 0.2f * sc;           // leaky_relu slope 0.2
    g_p[e] = sc;
    atomicMax(&g_m[d], enc_f(sc));
}

__global__ void edge_expsum(const int* __restrict__ dst) {
    int e = blockIdx.x * blockDim.x + threadIdx.x;
    if (e >= E_PER) return;
    int d = dst[e];
    float p = __expf(g_p[e] - dec_f(g_m[d]));
    g_p[e] = p;
    atomicAdd(&g_z[d], p);
}

// warp per edge: tmp[dst] += alpha * x[src]
__global__ void edge_scatter(const int* __restrict__ src, const int* __restrict__ dst,
                             const float* __restrict__ xs_ext, int buf, int soff) {
    int warp = threadIdx.x >> 5, lane = threadIdx.x & 31;
    int e = blockIdx.x * 8 + warp;
    if (e >= E_PER) return;
    int s = src[e], d = dst[e];
    float a = g_p[e] / (g_z[d] + 1e-16f);
    const float* x = in_feat(xs_ext, buf, soff);
    size_t sb = (size_t)s * H, db = (size_t)d * H;
    atomicAdd(&g_tmp[db + lane],      x[sb + lane]      * a);
    atomicAdd(&g_tmp[db + 32 + lane], x[sb + 32 + lane] * a);
}

// C[M,64] += g_tmp[M,64] @ W[64,64]   (64 threads, 8x8 register tiles)
__global__ void gemm_acc(const float* __restrict__ W, int outbuf, int doff, int M) {
    __shared__ float AsT[64][68];    // k-major (transposed) A tile, padded
    __shared__ float Wsm[64 * 64];
    int tid = threadIdx.x;           // 64
    int row0 = blockIdx.x * 64;
    float* C = ((outbuf == 0) ? g_feat0 : g_feat1) + (size_t)doff * H;

    const float4* W4 = (const float4*)W;
    float4* Ws4 = (float4*)Wsm;
    #pragma unroll
    for (int i = 0; i < 16; i++) Ws4[tid + i * 64] = W4[tid + i * 64];

    const float4* A4 = (const float4*)g_tmp;
    #pragma unroll
    for (int i = 0; i < 16; i++) {
        int idx = tid + i * 64;          // 0..1023
        int r = idx >> 4;                // row within tile
        int c4 = idx & 15;               // float4 column group
        float4 v = make_float4(0.f, 0.f, 0.f, 0.f);
        if (row0 + r < M) v = A4[(size_t)(row0 + r) * 16 + c4];
        AsT[c4 * 4 + 0][r] = v.x;
        AsT[c4 * 4 + 1][r] = v.y;
        AsT[c4 * 4 + 2][r] = v.z;
        AsT[c4 * 4 + 3][r] = v.w;
    }
    __syncthreads();

    int tx = tid & 7, ty = tid >> 3;
    float acc[8][8];
    #pragma unroll
    for (int i = 0; i < 8; i++)
        #pragma unroll
        for (int j = 0; j < 8; j++) acc[i][j] = 0.f;

    #pragma unroll
    for (int k = 0; k < 64; k++) {
        float4 a0 = *(const float4*)&AsT[k][ty * 8];
        float4 a1 = *(const float4*)&AsT[k][ty * 8 + 4];
        float4 b0 = *(const float4*)&Wsm[k * 64 + tx * 8];
        float4 b1 = *(const float4*)&Wsm[k * 64 + tx * 8 + 4];
        float av[8] = {a0.x, a0.y, a0.z, a0.w, a1.x, a1.y, a1.z, a1.w};
        float bv[8] = {b0.x, b0.y, b0.z, b0.w, b1.x, b1.y, b1.z, b1.w};
        #pragma unroll
        for (int i = 0; i < 8; i++)
            #pragma unroll
            for (int j = 0; j < 8; j++) acc[i][j] += av[i] * bv[j];
    }

    #pragma unroll
    for (int i = 0; i < 8; i++) {
        int r = row0 + ty * 8 + i;
        if (r < M) {
            float4* c4 = (float4*)&C[(size_t)r * H + tx * 8];
            float4 v0 = c4[0], v1 = c4[1];
            v0.x += acc[i][0]; v0.y += acc[i][1]; v0.z += acc[i][2]; v0.w += acc[i][3];
            v1.x += acc[i][4]; v1.y += acc[i][5]; v1.z += acc[i][6]; v1.w += acc[i][7];
            c4[0] = v0; c4[1] = v1;
        }
    }
}

// x = relu(acc + sum of biases of relations targeting this node type)
__global__ void relu_bias(int buf, const float* __restrict__ bias, int l) {
    int idx = blockIdx.x * blockDim.x + threadIdx.x;
    if (idx >= NTOT * H) return;
    int j = idx & (H - 1);
    const float* b = bias + l * 9 * H;
    float s;
    if (idx < N0 * H)                 s = b[5*H+j] + b[6*H+j] + b[7*H+j];   // type0 <- rels 5,6,7
    else if (idx < (N0+N1) * H)       s = b[0*H+j];                          // type1 <- rel 0
    else if (idx < (N0+N1+N2) * H)    s = b[1*H+j] + b[8*H+j];               // type2 <- rels 1,8
    else                              s = b[2*H+j] + b[3*H+j] + b[4*H+j];    // type3 <- rels 2,3,4
    float* p = (buf == 0) ? g_feat0 : g_feat1;
    float v = p[idx] + s;
    p[idx] = v > 0.f ? v : 0.f;
}

__global__ void pool_zero() {
    int i = blockIdx.x * blockDim.x + threadIdx.x;
    if (i < NB * 2 * H) g_pool[i] = 0.f;
    if (i < 2 * NB)     g_cnt[i]  = 0.f;
}

// warp per node over variable (type0) then constraint (type3) nodes of g_feat1
__global__ void pool_kernel(const int* __restrict__ bvar, const int* __restrict__ bcon) {
    int warp = threadIdx.x >> 5, lane = threadIdx.x & 31;
    int gw = blockIdx.x * 8 + warp;
    if (gw < N0) {
        int b = bvar[gw];
        size_t base = (size_t)gw * H;
        atomicAdd(&g_pool[b * 128 + lane],      g_feat1[base + lane]);
        atomicAdd(&g_pool[b * 128 + 32 + lane], g_feat1[base + 32 + lane]);
        if (lane == 0) atomicAdd(&g_cnt[b], 1.f);
    } else if (gw < N0 + N3) {
        int j = gw - N0;
        int b = bcon[j];
        const float* xc = g_feat1 + (size_t)(N0 + N1 + N2) * H;
        size_t base = (size_t)j * H;
        atomicAdd(&g_pool[b * 128 + 64 + lane], xc[base + lane]);
        atomicAdd(&g_pool[b * 128 + 96 + lane], xc[base + 32 + lane]);
        if (lane == 0) atomicAdd(&g_cnt[NB + b], 1.f);
    }
}

__global__ void final_kernel(const float* __restrict__ lw, const float* __restrict__ lb,
                             float* __restrict__ out) {
    int t = threadIdx.x;   // 128
    if (t >= 128) return;
    int b = t >> 1, o = t & 1;
    float cv = fmaxf(g_cnt[b], 1.f);
    float cc = fmaxf(g_cnt[NB + b], 1.f);
    float s = lb[o];
    #pragma unroll
    for (int j = 0; j < H; j++) {
        s += (g_pool[b * 128 + j]      / cv) * lw[o * 128 + j];
        s += (g_pool[b * 128 + 64 + j] / cc) * lw[o * 128 + 64 + j];
    }
    out[b * 2 + o] = s;
}

// ---------------------------------- launcher -------------------------------------
extern "C" void kernel_launch(void* const* d_in, const int* in_sizes, int n_in,
                              void* d_out, int out_size) {
    const float* xin[4] = {(const float*)d_in[0], (const float*)d_in[1],
                           (const float*)d_in[2], (const float*)d_in[3]};
    const float* Wsrc = (const float*)d_in[4];
    const float* Wdst = (const float*)d_in[5];
    const float* asrc = (const float*)d_in[6];
    const float* adst = (const float*)d_in[7];
    const float* bias = (const float*)d_in[8];
    const float* lw   = (const float*)d_in[9];
    const float* lb   = (const float*)d_in[10];
    const int* srcs[9]; const int* dsts[9];
    for (int r = 0; r < 9; r++) {
        srcs[r] = (const int*)d_in[11 + 2 * r];
        dsts[r] = (const int*)d_in[12 + 2 * r];
    }
    const int* bvar = (const int*)d_in[29];
    const int* bcon = (const int*)d_in[30];

    static const int RS[9]   = {0, 0, 0, 2, 3, 1, 2, 3, 3};
    static const int RD[9]   = {1, 2, 3, 3, 3, 0, 0, 0, 2};
    static const int NSZ[4]  = {N0, N1, N2, N3};
    static const int OFFN[4] = {0, N0, N0 + N1, N0 + N1 + N2};

    for (int l = 0; l < 2; l++) {
        int outbuf = l;                 // 0 for layer0, 1 for layer1
        int inbuf  = (l == 0) ? -1 : 0; // -1 => external d_in features
        zero_feat<<<(NTOT * H / 4 + 255) / 256, 256>>>(outbuf);
        for (int r = 0; r < 9; r++) {
            int s = RS[r], d = RD[r];
            int Ns = NSZ[s], Nd = NSZ[d];
            const float* Wsp = Wsrc + (size_t)(l * 9 + r) * H * H;
            const float* Wdp = Wdst + (size_t)(l * 9 + r) * H * H;
            const float* asp = asrc + (size_t)(l * 9 + r) * H;
            const float* adp = adst + (size_t)(l * 9 + r) * H;

            prep_kernel<<<1, 128>>>(Wsp, asp, Wdp, adp);
            alpha_kernel<<<(Ns + Nd + 7) / 8, 256>>>(xin[s], xin[d], inbuf,
                                                     OFFN[s], OFFN[d], Ns, Nd);
            edge_score_max<<<(E_PER + 255) / 256, 256>>>(srcs[r], dsts[r]);
            edge_expsum<<<(E_PER + 255) / 256, 256>>>(dsts[r]);
            edge_scatter<<<(E_PER + 7) / 8, 256>>>(srcs[r], dsts[r], xin[s], inbuf, OFFN[s]);
            gemm_acc<<<(Nd + 63) / 64, 64>>>(Wsp, outbuf, OFFN[d], Nd);
        }
        relu_bias<<<(NTOT * H + 255) / 256, 256>>>(outbuf, bias, l);
    }
    pool_zero<<<(NB * 2 * H + 255) / 256, 256>>>();
    pool_kernel<<<(N0 + N3 + 7) / 8, 256>>>(bvar, bcon);
    final_kernel<<<1, 128>>>(lw, lb, (float*)d_out);
}

// round 2
// speedup vs baseline: 1.5451x; 1.5451x over previous
#include <cuda_runtime.h>

#define H      64
#define E_PER  300000
#define RTOT   9
#define ETOT   (RTOT * E_PER)
#define NB     64
#define N0     100000
#define N1     20000
#define N2     50000
#define N3     80000
#define NTOT   250000
#define NMAX   100000

// ---------------- static device scratch ----------------
__device__ float g_feat0[NTOT * H];                 // layer-0 output (pre-relu)
__device__ float g_feat1[NTOT * H];                 // layer-1 output (pre-relu)
__device__ float g_hs[(size_t)RTOT * NMAX * H];     // per-relation transformed src feats
__device__ float g_als[RTOT * NMAX];
__device__ float g_ald[RTOT * NMAX];
__device__ float g_z[RTOT * NMAX];
__device__ float g_p[ETOT];
__device__ float g_wsv[RTOT * H];                   // Wsrc @ asrc per relation
__device__ float g_wdv[RTOT * H];                   // Wdst @ adst per relation
__device__ float g_pool[NB * 2 * H];
__device__ float g_cnt[2 * NB];

__constant__ int c_ST[9]  = {0, 0, 0, 2, 3, 1, 2, 3, 3};
__constant__ int c_DT[9]  = {1, 2, 3, 3, 3, 0, 0, 0, 2};
__constant__ int c_NSZ[4] = {N0, N1, N2, N3};
__constant__ int c_OFF[4] = {0, N0, N0 + N1, N0 + N1 + N2};

struct XP { const float* x[4]; };
struct EP { const int* s[9]; const int* d[9]; };

// ---------------------------------- kernels -------------------------------------

// block r: wsv[r][k] = sum_j Wsrc[r][k][j]*asrc[r][j]; same for dst
__global__ void prep(const float* __restrict__ Ws_l, const float* __restrict__ as_l,
                     const float* __restrict__ Wd_l, const float* __restrict__ ad_l) {
    int r = blockIdx.x, t = threadIdx.x;
    const float* W; const float* a; float* o; int k;
    if (t < 64) { W = Ws_l + r * 4096; a = as_l + r * 64; o = g_wsv + r * 64; k = t; }
    else        { W = Wd_l + r * 4096; a = ad_l + r * 64; o = g_wdv + r * 64; k = t - 64; }
    float s = 0.f;
    #pragma unroll
    for (int j = 0; j < 64; j++) s += W[k * 64 + j] * a[j];
    o[k] = s;
}

// hs_r = act(x[stype(r)]) @ Wsrc_r  for all 9 relations (grid.y = r)
__global__ void hs_gemm(XP xp, const float* __restrict__ Ws_l, int use_feat) {
    int r = blockIdx.y;
    int st = c_ST[r];
    int Ns = c_NSZ[st];
    int row0 = blockIdx.x * 64;
    if (row0 >= Ns) return;
    const float* x = use_feat ? (g_feat0 + (size_t)c_OFF[st] * H) : xp.x[st];
    const float* W = Ws_l + (size_t)r * H * H;
    float* hsout = g_hs + (size_t)r * NMAX * H;

    __shared__ float AsT[64][68];
    __shared__ float Wsm[64 * 64];
    int tid = threadIdx.x;   // 64

    const float4* W4 = (const float4*)W;
    float4* Ws4 = (float4*)Wsm;
    #pragma unroll
    for (int i = 0; i < 16; i++) Ws4[tid + i * 64] = W4[tid + i * 64];

    const float4* A4 = (const float4*)x;
    #pragma unroll
    for (int i = 0; i < 16; i++) {
        int idx = tid + i * 64;
        int rr = idx >> 4;
        int c4 = idx & 15;
        float4 v = make_float4(0.f, 0.f, 0.f, 0.f);
        if (row0 + rr < Ns) v = A4[(size_t)(row0 + rr) * 16 + c4];
        if (use_feat) { v.x = fmaxf(v.x, 0.f); v.y = fmaxf(v.y, 0.f);
                        v.z = fmaxf(v.z, 0.f); v.w = fmaxf(v.w, 0.f); }
        AsT[c4 * 4 + 0][rr] = v.x;
        AsT[c4 * 4 + 1][rr] = v.y;
        AsT[c4 * 4 + 2][rr] = v.z;
        AsT[c4 * 4 + 3][rr] = v.w;
    }
    __syncthreads();

    int tx = tid & 7, ty = tid >> 3;
    float acc[8][8];
    #pragma unroll
    for (int i = 0; i < 8; i++)
        #pragma unroll
        for (int j = 0; j < 8; j++) acc[i][j] = 0.f;

    #pragma unroll
    for (int k = 0; k < 64; k++) {
        float4 a0 = *(const float4*)&AsT[k][ty * 8];
        float4 a1 = *(const float4*)&AsT[k][ty * 8 + 4];
        float4 b0 = *(const float4*)&Wsm[k * 64 + tx * 8];
        float4 b1 = *(const float4*)&Wsm[k * 64 + tx * 8 + 4];
        float av[8] = {a0.x, a0.y, a0.z, a0.w, a1.x, a1.y, a1.z, a1.w};
        float bv[8] = {b0.x, b0.y, b0.z, b0.w, b1.x, b1.y, b1.z, b1.w};
        #pragma unroll
        for (int i = 0; i < 8; i++)
            #pragma unroll
            for (int j = 0; j < 8; j++) acc[i][j] += av[i] * bv[j];
    }

    #pragma unroll
    for (int i = 0; i < 8; i++) {
        int rr = row0 + ty * 8 + i;
        if (rr < Ns) {
            float4* c4 = (float4*)(hsout + (size_t)rr * H + tx * 8);
            c4[0] = make_float4(acc[i][0], acc[i][1], acc[i][2], acc[i][3]);
            c4[1] = make_float4(acc[i][4], acc[i][5], acc[i][6], acc[i][7]);
        }
    }
}

// warp per node: attention logits for every (relation, side) combo of its type
__global__ void alpha_all(XP xp, int use_feat) {
    int warp = threadIdx.x >> 5, lane = threadIdx.x & 31;
    int gw = blockIdx.x * 8 + warp;
    if (gw >= NTOT) return;
    int t = (gw < N0) ? 0 : (gw < N0 + N1) ? 1 : (gw < N0 + N1 + N2) ? 2 : 3;
    int li = gw - c_OFF[t];
    const float* x = use_feat ? (g_feat0 + (size_t)c_OFF[t] * H) : xp.x[t];
    float x0 = x[(size_t)li * H + lane];
    float x1 = x[(size_t)li * H + 32 + lane];
    if (use_feat) { x0 = fmaxf(x0, 0.f); x1 = fmaxf(x1, 0.f); }
    #pragma unroll
    for (int r = 0; r < 9; r++) {
        if (c_ST[r] == t) {
            float v = x0 * g_wsv[r * 64 + lane] + x1 * g_wsv[r * 64 + 32 + lane];
            #pragma unroll
            for (int o = 16; o; o >>= 1) v += __shfl_xor_sync(0xffffffffu, v, o);
            if (lane == 0) g_als[r * NMAX + li] = v;
        }
        if (c_DT[r] == t) {
            float v = x0 * g_wdv[r * 64 + lane] + x1 * g_wdv[r * 64 + 32 + lane];
            #pragma unroll
            for (int o = 16; o; o >>= 1) v += __shfl_xor_sync(0xffffffffu, v, o);
            if (lane == 0) { g_ald[r * NMAX + li] = v; g_z[r * NMAX + li] = 0.f; }
        }
    }
}

// feat[buf] = sum of biases of relations targeting this node type (pre-relu accum)
__global__ void feat_init(const float* __restrict__ bias_l, int buf) {
    int idx = blockIdx.x * blockDim.x + threadIdx.x;
    if (idx >= NTOT * H) return;
    int j = idx & 63;
    float s;
    if (idx < N0 * H)                s = bias_l[5*64+j] + bias_l[6*64+j] + bias_l[7*64+j];
    else if (idx < (N0+N1) * H)      s = bias_l[0*64+j];
    else if (idx < (N0+N1+N2) * H)   s = bias_l[1*64+j] + bias_l[8*64+j];
    else                             s = bias_l[2*64+j] + bias_l[3*64+j] + bias_l[4*64+j];
    ((buf == 0) ? g_feat0 : g_feat1)[idx] = s;
}

// all 2.7M edges: p = exp(leaky(als+ald)); z[dst] += p   (max-shift dropped: exact ratio)
__global__ void edge_p(EP ep) {
    int idx = blockIdx.x * blockDim.x + threadIdx.x;
    if (idx >= ETOT) return;
    int r = idx / E_PER;
    int e = idx - r * E_PER;
    int s = __ldg(&ep.s[r][e]);
    int d = __ldg(&ep.d[r][e]);
    float sc = g_als[r * NMAX + s] + g_ald[r * NMAX + d];
    sc = sc > 0.f ? sc : 0.2f * sc;
    float p = __expf(sc);
    g_p[idx] = p;
    atomicAdd(&g_z[r * NMAX + d], p);
}

// 16 lanes per edge: feat[dst] += (p/z) * hs[src]  via 128-bit vector RED
__global__ void scatter(EP ep, int buf) {
    int gt = blockIdx.x * blockDim.x + threadIdx.x;
    int ed = gt >> 4;
    int q  = gt & 15;
    if (ed >= ETOT) return;
    int r = ed / E_PER;
    int e = ed - r * E_PER;
    int s = __ldg(&ep.s[r][e]);
    int d = __ldg(&ep.d[r][e]);
    float z = g_z[r * NMAX + d];
    float a = __fdividef(g_p[ed], z + 1e-16f);
    const float4* hs4 = (const float4*)(g_hs + (size_t)r * NMAX * H);
    float4 v = hs4[(size_t)s * 16 + q];
    float4 w = make_float4(v.x * a, v.y * a, v.z * a, v.w * a);
    float* fb = (buf == 0) ? g_feat0 : g_feat1;
    float4* f4 = (float4*)(fb + (size_t)(c_OFF[c_DT[r]] + d) * H);
    atomicAdd(&f4[q], w);
}

__global__ void pool_zero() {
    int i = blockIdx.x * blockDim.x + threadIdx.x;
    if (i < NB * 2 * H) g_pool[i] = 0.f;
    if (i < 2 * NB)     g_cnt[i]  = 0.f;
}

// warp per node: pooled sums of relu(feat1) for variable (t0) and constraint (t3)
__global__ void pool_kernel(const int* __restrict__ bvar, const int* __restrict__ bcon) {
    int warp = threadIdx.x >> 5, lane = threadIdx.x & 31;
    int gw = blockIdx.x * 8 + warp;
    if (gw < N0) {
        int b = bvar[gw];
        size_t base = (size_t)gw * H;
        atomicAdd(&g_pool[b * 128 + lane],      fmaxf(g_feat1[base + lane], 0.f));
        atomicAdd(&g_pool[b * 128 + 32 + lane], fmaxf(g_feat1[base + 32 + lane], 0.f));
        if (lane == 0) atomicAdd(&g_cnt[b], 1.f);
    } else if (gw < N0 + N3) {
        int j = gw - N0;
        int b = bcon[j];
        const float* xc = g_feat1 + (size_t)(N0 + N1 + N2) * H;
        size_t base = (size_t)j * H;
        atomicAdd(&g_pool[b * 128 + 64 + lane], fmaxf(xc[base + lane], 0.f));
        atomicAdd(&g_pool[b * 128 + 96 + lane], fmaxf(xc[base + 32 + lane], 0.f));
        if (lane == 0) atomicAdd(&g_cnt[NB + b], 1.f);
    }
}

__global__ void final_kernel(const float* __restrict__ lw, const float* __restrict__ lb,
                             float* __restrict__ out) {
    int t = threadIdx.x;   // 128
    if (t >= 128) return;
    int b = t >> 1, o = t & 1;
    float cv = fmaxf(g_cnt[b], 1.f);
    float cc = fmaxf(g_cnt[NB + b], 1.f);
    float s = lb[o];
    #pragma unroll
    for (int j = 0; j < H; j++) {
        s += (g_pool[b * 128 + j]      / cv) * lw[o * 128 + j];
        s += (g_pool[b * 128 + 64 + j] / cc) * lw[o * 128 + 64 + j];
    }
    out[b * 2 + o] = s;
}

// ---------------------------------- launcher -------------------------------------
extern "C" void kernel_launch(void* const* d_in, const int* in_sizes, int n_in,
                              void* d_out, int out_size) {
    XP xp;
    for (int t = 0; t < 4; t++) xp.x[t] = (const float*)d_in[t];
    const float* Wsrc = (const float*)d_in[4];
    const float* Wdst = (const float*)d_in[5];
    const float* asrc = (const float*)d_in[6];
    const float* adst = (const float*)d_in[7];
    const float* bias = (const float*)d_in[8];
    const float* lw   = (const float*)d_in[9];
    const float* lb   = (const float*)d_in[10];
    EP ep;
    for (int r = 0; r < 9; r++) {
        ep.s[r] = (const int*)d_in[11 + 2 * r];
        ep.d[r] = (const int*)d_in[12 + 2 * r];
    }
    const int* bvar = (const int*)d_in[29];
    const int* bcon = (const int*)d_in[30];

    for (int l = 0; l < 2; l++) {
        const float* Ws_l = Wsrc + (size_t)l * 9 * 4096;
        const float* Wd_l = Wdst + (size_t)l * 9 * 4096;
        const float* as_l = asrc + (size_t)l * 9 * 64;
        const float* ad_l = adst + (size_t)l * 9 * 64;
        const float* b_l  = bias + (size_t)l * 9 * 64;

        prep<<<9, 128>>>(Ws_l, as_l, Wd_l, ad_l);
        hs_gemm<<<dim3((NMAX + 63) / 64, 9), 64>>>(xp, Ws_l, l);
        alpha_all<<<(NTOT + 7) / 8, 256>>>(xp, l);
        feat_init<<<(NTOT * H + 255) / 256, 256>>>(b_l, l);
        edge_p<<<(ETOT + 255) / 256, 256>>>(ep);
        scatter<<<(ETOT * 16 + 255) / 256, 256>>>(ep, l);
    }
    pool_zero<<<(NB * 2 * H + 255) / 256, 256>>>();
    pool_kernel<<<(N0 + N3 + 7) / 8, 256>>>(bvar, bcon);
    final_kernel<<<1, 128>>>(lw, lb, (float*)d_out);
}

// round 3
// speedup vs baseline: 1.8758x; 1.2141x over previous
#include <cuda_runtime.h>

#define H      64
#define E_PER  300000
#define RTOT   9
#define ETOT   (RTOT * E_PER)
#define NB     64
#define N0     100000
#define N1     20000
#define N2     50000
#define N3     80000
#define NTOT   250000
#define NMAX   100000

// ---------------- static device scratch ----------------
__device__ float g_feat0[NTOT * H];
__device__ float g_feat1[NTOT * H];
__device__ float g_hs[(size_t)RTOT * NMAX * H];
__device__ float g_als[RTOT * NMAX];
__device__ float g_ald[RTOT * NMAX];
__device__ float g_z[RTOT * NMAX];
__device__ float g_p[ETOT];
__device__ float g_wsv[RTOT * H];
__device__ float g_wdv[RTOT * H];
__device__ float g_pool[NB * 2 * H];
__device__ float g_cnt[2 * NB];

__constant__ int c_ST[9]  = {0, 0, 0, 2, 3, 1, 2, 3, 3};
__constant__ int c_DT[9]  = {1, 2, 3, 3, 3, 0, 0, 0, 2};
__constant__ int c_NSZ[4] = {N0, N1, N2, N3};
__constant__ int c_OFF[4] = {0, N0, N0 + N1, N0 + N1 + N2};
// relations with src type t (group == src type)
__constant__ int c_GN[4]     = {3, 1, 2, 3};
__constant__ int c_GR[4][3]  = {{0, 1, 2}, {5, 0, 0}, {3, 6, 0}, {4, 7, 8}};
// relations targeting type t (for bias init), -1 padded
__constant__ int c_TB[4][3]  = {{5, 6, 7}, {0, -1, -1}, {1, 8, -1}, {2, 3, 4}};

struct XP { const float* x[4]; };
struct EP { const int* s[9]; const int* d[9]; };

// ---------------------------- tf32 helpers ----------------------------
__device__ __forceinline__ unsigned f2tf(float f) {
    unsigned u;
    asm("cvt.rna.tf32.f32 %0, %1;" : "=r"(u) : "f"(f));
    return u;
}
__device__ __forceinline__ void mma8(float* c, const unsigned* a, unsigned b0, unsigned b1) {
    asm volatile(
        "mma.sync.aligned.m16n8k8.row.col.f32.tf32.tf32.f32 "
        "{%0,%1,%2,%3},{%4,%5,%6,%7},{%8,%9},{%0,%1,%2,%3};"
        : "+f"(c[0]), "+f"(c[1]), "+f"(c[2]), "+f"(c[3])
        : "r"(a[0]), "r"(a[1]), "r"(a[2]), "r"(a[3]), "r"(b0), "r"(b1));
}

// ---------------------------------- kernels -------------------------------------

// block r: wsv[r][k] = sum_j Wsrc[r][k][j]*asrc[r][j]; same for dst
__global__ void prep(const float* __restrict__ Ws_l, const float* __restrict__ as_l,
                     const float* __restrict__ Wd_l, const float* __restrict__ ad_l) {
    int r = blockIdx.x, t = threadIdx.x;
    const float* W; const float* a; float* o; int k;
    if (t < 64) { W = Ws_l + r * 4096; a = as_l + r * 64; o = g_wsv + r * 64; k = t; }
    else        { W = Wd_l + r * 4096; a = ad_l + r * 64; o = g_wdv + r * 64; k = t - 64; }
    float s = 0.f;
    #pragma unroll
    for (int j = 0; j < 64; j++) s += W[k * 64 + j] * a[j];
    o[k] = s;
}

// hs_r = act(x[stype]) @ Wsrc_r via tf32 mma with 3-term compensation.
// grid.y = src type (A tile loaded once, reused for all its relations).
__global__ void __launch_bounds__(128) hs_mma(XP xp, const float* __restrict__ Ws_l,
                                              int use_feat) {
    __shared__ float sA[64 * 72];
    __shared__ float sW[64 * 72];
    int g = blockIdx.y;                 // src type
    int Ns = c_NSZ[g];
    int row0 = blockIdx.x * 64;
    if (row0 >= Ns) return;
    const float* x = use_feat ? (g_feat0 + (size_t)c_OFF[g] * H) : xp.x[g];
    int tid = threadIdx.x;

    const float4* A4 = (const float4*)x;
    #pragma unroll
    for (int i = 0; i < 8; i++) {
        int idx = tid + i * 128;        // 0..1023 float4 slots
        int r = idx >> 4, c4 = idx & 15;
        float4 v = make_float4(0.f, 0.f, 0.f, 0.f);
        if (row0 + r < Ns) v = A4[(size_t)(row0 + r) * 16 + c4];
        if (use_feat) { v.x = fmaxf(v.x, 0.f); v.y = fmaxf(v.y, 0.f);
                        v.z = fmaxf(v.z, 0.f); v.w = fmaxf(v.w, 0.f); }
        float* dst = sA + r * 72 + c4 * 4;
        dst[0] = v.x; dst[1] = v.y; dst[2] = v.z; dst[3] = v.w;
    }

    int warp = tid >> 5, lane = tid & 31;
    int gid = lane >> 2, tig = lane & 3;
    int mrow = warp * 16;

    int nrel = c_GN[g];
    for (int ri = 0; ri < nrel; ri++) {
        int r = c_GR[g][ri];
        __syncthreads();                // A ready / sW safe to overwrite
        const float4* W4 = (const float4*)(Ws_l + (size_t)r * 4096);
        #pragma unroll
        for (int i = 0; i < 8; i++) {
            int idx = tid + i * 128;
            int rr = idx >> 4, c4 = idx & 15;
            float4 v = W4[idx];
            float* dst = sW + rr * 72 + c4 * 4;
            dst[0] = v.x; dst[1] = v.y; dst[2] = v.z; dst[3] = v.w;
        }
        __syncthreads();

        float acc[8][4];
        #pragma unroll
        for (int n = 0; n < 8; n++)
            #pragma unroll
            for (int j = 0; j < 4; j++) acc[n][j] = 0.f;

        #pragma unroll
        for (int k0 = 0; k0 < 8; k0++) {
            float af[4];
            af[0] = sA[(mrow + gid)     * 72 + k0 * 8 + tig];
            af[1] = sA[(mrow + gid + 8) * 72 + k0 * 8 + tig];
            af[2] = sA[(mrow + gid)     * 72 + k0 * 8 + tig + 4];
            af[3] = sA[(mrow + gid + 8) * 72 + k0 * 8 + tig + 4];
            unsigned as_[4], ar_[4];
            #pragma unroll
            for (int j = 0; j < 4; j++) {
                as_[j] = f2tf(af[j]);
                ar_[j] = f2tf(af[j] - __uint_as_float(as_[j]));
            }
            #pragma unroll
            for (int n0 = 0; n0 < 8; n0++) {
                float bf0 = sW[(k0 * 8 + tig)     * 72 + n0 * 8 + gid];
                float bf1 = sW[(k0 * 8 + tig + 4) * 72 + n0 * 8 + gid];
                unsigned bs0 = f2tf(bf0), bs1 = f2tf(bf1);
                unsigned br0 = f2tf(bf0 - __uint_as_float(bs0));
                unsigned br1 = f2tf(bf1 - __uint_as_float(bs1));
                mma8(acc[n0], as_, bs0, bs1);
                mma8(acc[n0], ar_, bs0, bs1);
                mma8(acc[n0], as_, br0, br1);
            }
        }

        float* hsout = g_hs + (size_t)r * NMAX * H;
        int rr0 = row0 + mrow + gid;
        int rr1 = rr0 + 8;
        #pragma unroll
        for (int n0 = 0; n0 < 8; n0++) {
            int cc = n0 * 8 + 2 * tig;
            if (rr0 < Ns) {
                float2* p = (float2*)(hsout + (size_t)rr0 * H + cc);
                *p = make_float2(acc[n0][0], acc[n0][1]);
            }
            if (rr1 < Ns) {
                float2* p = (float2*)(hsout + (size_t)rr1 * H + cc);
                *p = make_float2(acc[n0][2], acc[n0][3]);
            }
        }
    }
}

// warp per node: attention logits for every (relation, side) of its type,
// plus bias-initialization of the output feature buffer (fused feat_init).
__global__ void alpha_all(XP xp, int use_feat, const float* __restrict__ bias_l,
                          int outbuf) {
    int warp = threadIdx.x >> 5, lane = threadIdx.x & 31;
    int gw = blockIdx.x * 8 + warp;
    if (gw >= NTOT) return;
    int t = (gw < N0) ? 0 : (gw < N0 + N1) ? 1 : (gw < N0 + N1 + N2) ? 2 : 3;
    int li = gw - c_OFF[t];
    const float* x = use_feat ? (g_feat0 + (size_t)c_OFF[t] * H) : xp.x[t];
    float x0 = x[(size_t)li * H + lane];
    float x1 = x[(size_t)li * H + 32 + lane];
    if (use_feat) { x0 = fmaxf(x0, 0.f); x1 = fmaxf(x1, 0.f); }
    #pragma unroll
    for (int r = 0; r < 9; r++) {
        if (c_ST[r] == t) {
            float v = x0 * g_wsv[r * 64 + lane] + x1 * g_wsv[r * 64 + 32 + lane];
            #pragma unroll
            for (int o = 16; o; o >>= 1) v += __shfl_xor_sync(0xffffffffu, v, o);
            if (lane == 0) g_als[r * NMAX + li] = v;
        }
        if (c_DT[r] == t) {
            float v = x0 * g_wdv[r * 64 + lane] + x1 * g_wdv[r * 64 + 32 + lane];
            #pragma unroll
            for (int o = 16; o; o >>= 1) v += __shfl_xor_sync(0xffffffffu, v, o);
            if (lane == 0) { g_ald[r * NMAX + li] = v; g_z[r * NMAX + li] = 0.f; }
        }
    }
    // fused feat_init: out-feature buffer = sum of biases of relations targeting t
    float s0 = 0.f, s1 = 0.f;
    #pragma unroll
    for (int i = 0; i < 3; i++) {
        int r = c_TB[t][i];
        if (r >= 0) {
            s0 += bias_l[r * 64 + lane];
            s1 += bias_l[r * 64 + 32 + lane];
        }
    }
    float* fb = (outbuf == 0) ? g_feat0 : g_feat1;
    fb[(size_t)gw * H + lane]      = s0;
    fb[(size_t)gw * H + 32 + lane] = s1;
}

// all 2.7M edges: p = exp(leaky(als+ald)); z[dst] += p  (max-shift dropped: exact ratio)
__global__ void edge_p(EP ep) {
    int idx = blockIdx.x * blockDim.x + threadIdx.x;
    if (idx >= ETOT) return;
    int r = idx / E_PER;
    int e = idx - r * E_PER;
    int s = __ldg(&ep.s[r][e]);
    int d = __ldg(&ep.d[r][e]);
    float sc = g_als[r * NMAX + s] + g_ald[r * NMAX + d];
    sc = sc > 0.f ? sc : 0.2f * sc;
    float p = __expf(sc);
    g_p[idx] = p;
    atomicAdd(&g_z[r * NMAX + d], p);
}

// 16 lanes per edge: feat[dst] += (p/z) * hs[src]  via 128-bit vector RED
__global__ void scatter(EP ep, int buf) {
    int gt = blockIdx.x * blockDim.x + threadIdx.x;
    int ed = gt >> 4;
    int q  = gt & 15;
    if (ed >= ETOT) return;
    int r = ed / E_PER;
    int e = ed - r * E_PER;
    int s = __ldg(&ep.s[r][e]);
    int d = __ldg(&ep.d[r][e]);
    float z = g_z[r * NMAX + d];
    float a = __fdividef(g_p[ed], z + 1e-16f);
    const float4* hs4 = (const float4*)(g_hs + (size_t)r * NMAX * H);
    float4 v = hs4[(size_t)s * 16 + q];
    float4 w = make_float4(v.x * a, v.y * a, v.z * a, v.w * a);
    float* fb = (buf == 0) ? g_feat0 : g_feat1;
    float4* f4 = (float4*)(fb + (size_t)(c_OFF[c_DT[r]] + d) * H);
    atomicAdd(&f4[q], w);
}

__global__ void pool_zero() {
    int i = blockIdx.x * blockDim.x + threadIdx.x;
    if (i < NB * 2 * H) g_pool[i] = 0.f;
    if (i < 2 * NB)     g_cnt[i]  = 0.f;
}

__global__ void pool_kernel(const int* __restrict__ bvar, const int* __restrict__ bcon) {
    int warp = threadIdx.x >> 5, lane = threadIdx.x & 31;
    int gw = blockIdx.x * 8 + warp;
    if (gw < N0) {
        int b = bvar[gw];
        size_t base = (size_t)gw * H;
        atomicAdd(&g_pool[b * 128 + lane],      fmaxf(g_feat1[base + lane], 0.f));
        atomicAdd(&g_pool[b * 128 + 32 + lane], fmaxf(g_feat1[base + 32 + lane], 0.f));
        if (lane == 0) atomicAdd(&g_cnt[b], 1.f);
    } else if (gw < N0 + N3) {
        int j = gw - N0;
        int b = bcon[j];
        const float* xc = g_feat1 + (size_t)(N0 + N1 + N2) * H;
        size_t base = (size_t)j * H;
        atomicAdd(&g_pool[b * 128 + 64 + lane], fmaxf(xc[base + lane], 0.f));
        atomicAdd(&g_pool[b * 128 + 96 + lane], fmaxf(xc[base + 32 + lane], 0.f));
        if (lane == 0) atomicAdd(&g_cnt[NB + b], 1.f);
    }
}

__global__ void final_kernel(const float* __restrict__ lw, const float* __restrict__ lb,
                             float* __restrict__ out) {
    int t = threadIdx.x;
    if (t >= 128) return;
    int b = t >> 1, o = t & 1;
    float cv = fmaxf(g_cnt[b], 1.f);
    float cc = fmaxf(g_cnt[NB + b], 1.f);
    float s = lb[o];
    #pragma unroll
    for (int j = 0; j < H; j++) {
        s += (g_pool[b * 128 + j]      / cv) * lw[o * 128 + j];
        s += (g_pool[b * 128 + 64 + j] / cc) * lw[o * 128 + 64 + j];
    }
    out[b * 2 + o] = s;
}

// ---------------------------------- launcher -------------------------------------
extern "C" void kernel_launch(void* const* d_in, const int* in_sizes, int n_in,
                              void* d_out, int out_size) {
    XP xp;
    for (int t = 0; t < 4; t++) xp.x[t] = (const float*)d_in[t];
    const float* Wsrc = (const float*)d_in[4];
    const float* Wdst = (const float*)d_in[5];
    const float* asrc = (const float*)d_in[6];
    const float* adst = (const float*)d_in[7];
    const float* bias = (const float*)d_in[8];
    const float* lw   = (const float*)d_in[9];
    const float* lb   = (const float*)d_in[10];
    EP ep;
    for (int r = 0; r < 9; r++) {
        ep.s[r] = (const int*)d_in[11 + 2 * r];
        ep.d[r] = (const int*)d_in[12 + 2 * r];
    }
    const int* bvar = (const int*)d_in[29];
    const int* bcon = (const int*)d_in[30];

    for (int l = 0; l < 2; l++) {
        const float* Ws_l = Wsrc + (size_t)l * 9 * 4096;
        const float* Wd_l = Wdst + (size_t)l * 9 * 4096;
        const float* as_l = asrc + (size_t)l * 9 * 64;
        const float* ad_l = adst + (size_t)l * 9 * 64;
        const float* b_l  = bias + (size_t)l * 9 * 64;

        prep<<<9, 128>>>(Ws_l, as_l, Wd_l, ad_l);
        hs_mma<<<dim3((NMAX + 63) / 64, 4), 128>>>(xp, Ws_l, l);
        alpha_all<<<(NTOT + 7) / 8, 256>>>(xp, l, b_l, l);
        edge_p<<<(ETOT + 255) / 256, 256>>>(ep);
        scatter<<<(ETOT * 16 + 255) / 256, 256>>>(ep, l);
    }
    pool_zero<<<(NB * 2 * H + 255) / 256, 256>>>();
    pool_kernel<<<(N0 + N3 + 7) / 8, 256>>>(bvar, bcon);
    final_kernel<<<1, 128>>>(lw, lb, (float*)d_out);
}